// round 7
// baseline (speedup 1.0000x reference)
#include <cuda_runtime.h>
#include <cstdint>

#define NN 100000
#define EE 640000
#define HH 128
#define BN_EPS 1e-5f
#define NB 391            // ceil(NN/256)
#define GB 782            // ceil(NN/128)

// ---------------- device scratch ----------------
__device__ __align__(16) float g_y0[(size_t)NN * HH];
__device__ __align__(16) float g_y1[(size_t)NN * HH];
__device__ __align__(16) float g_wsh[3 * 128 * 256];   // layers 0-2 hi plane [layer][n][gk]
__device__ __align__(16) float g_wsl[3 * 128 * 256];   // lo plane
__device__ __align__(16) float g_ws1h[128 * 128];      // W1 hi
__device__ __align__(16) float g_ws1l[128 * 128];      // W1 lo
__device__ int   g_deg[NN];
__device__ int   g_off[NN + 1];
__device__ int   g_cur[NN];
__device__ int   g_ssrc[EE];
__device__ int   g_bpart[512];
__device__ int   g_bbase[512];
__device__ __align__(16) float g_cs[4 * 128];   // per-layer column sums (zeroed in prologue)
__device__ __align__(16) float g_cq[4 * 128];   // per-layer column sumsq

// ---------------- tf32 helpers ----------------
__device__ __forceinline__ uint32_t f2tf(float x) {
    uint32_t r;
    asm("cvt.rna.tf32.f32 %0, %1;" : "=r"(r) : "f"(x));
    return r;
}
__device__ __forceinline__ void tfsplit(float v, uint32_t& hi, uint32_t& lo) {
    hi = f2tf(v);
    lo = f2tf(v - __uint_as_float(hi));
}
__device__ __forceinline__ void mma8(float* c, const uint32_t* a, uint32_t b0, uint32_t b1) {
    asm("mma.sync.aligned.m16n8k8.row.col.f32.tf32.tf32.f32 "
        "{%0,%1,%2,%3},{%4,%5,%6,%7},{%8,%9},{%0,%1,%2,%3};"
        : "+f"(c[0]), "+f"(c[1]), "+f"(c[2]), "+f"(c[3])
        : "r"(a[0]), "r"(a[1]), "r"(a[2]), "r"(a[3]), "r"(b0), "r"(b1));
}

__device__ __forceinline__ float4 bnrelu4(float4 v, float4 m, float4 iv) {
    v.x = fmaxf(0.f, (v.x - m.x) * iv.x);
    v.y = fmaxf(0.f, (v.y - m.y) * iv.y);
    v.z = fmaxf(0.f, (v.z - m.z) * iv.z);
    v.w = fmaxf(0.f, (v.w - m.w) * iv.w);
    return v;
}

// ---------------- prologue: weight split + zero deg/cur/stats ----------------
__global__ void k_split(const float* __restrict__ Wl0, const float* __restrict__ Wr0,
                        const float* __restrict__ Wl1, const float* __restrict__ Wr1,
                        const float* __restrict__ Wl2, const float* __restrict__ Wr2,
                        const float* __restrict__ W1) {
    int i = blockIdx.x * 256 + threadIdx.x;
    if (i < NN) { g_deg[i] = 0; g_cur[i] = 0; }
    if (i < 512) { g_cs[i] = 0.f; g_cq[i] = 0.f; }
    if (i < 3 * 128 * 256) {
        int layer = i >> 15;
        int r = i & 32767;
        int n = r >> 8;
        int gk = r & 255;
        const float* W;
        int k = gk;
        if (gk < 128) {
            W = (layer == 0) ? Wl0 : ((layer == 1) ? Wl1 : Wl2);
        } else {
            W = (layer == 0) ? Wr0 : ((layer == 1) ? Wr1 : Wr2);
            k = gk - 128;
        }
        uint32_t hi, lo;
        tfsplit(W[n * 128 + k], hi, lo);
        g_wsh[i] = __uint_as_float(hi);
        g_wsl[i] = __uint_as_float(lo);
    } else if (i < 3 * 128 * 256 + 128 * 128) {
        int r = i - 98304;
        uint32_t hi, lo;
        tfsplit(W1[r], hi, lo);
        g_ws1h[r] = __uint_as_float(hi);
        g_ws1l[r] = __uint_as_float(lo);
    }
}

// ---------------- CSR build ----------------
__global__ void k_count(const int* __restrict__ dst) {
    int e = blockIdx.x * blockDim.x + threadIdx.x;
    if (e < EE) atomicAdd(&g_deg[dst[e]], 1);
}

__global__ void k_part() {
    __shared__ int ws[8];
    int i = blockIdx.x * 256 + threadIdx.x;
    int v = (i < NN) ? g_deg[i] : 0;
    int lane = threadIdx.x & 31, wid = threadIdx.x >> 5;
    int s = v;
#pragma unroll
    for (int o = 16; o; o >>= 1) s += __shfl_xor_sync(0xFFFFFFFFu, s, o);
    if (lane == 0) ws[wid] = s;
    __syncthreads();
    if (threadIdx.x == 0) {
        int t = 0;
#pragma unroll
        for (int w = 0; w < 8; w++) t += ws[w];
        g_bpart[blockIdx.x] = t;
    }
}

__global__ void k_scanp() {
    __shared__ int ws[16];
    int t = threadIdx.x;
    int lane = t & 31, wid = t >> 5;
    int v = (t < NB) ? g_bpart[t] : 0;
    int incl = v;
#pragma unroll
    for (int o = 1; o < 32; o <<= 1) {
        int u = __shfl_up_sync(0xFFFFFFFFu, incl, o);
        if (lane >= o) incl += u;
    }
    if (lane == 31) ws[wid] = incl;
    __syncthreads();
    if (wid == 0 && lane < 16) {
        int u = ws[lane];
#pragma unroll
        for (int o = 1; o < 16; o <<= 1) {
            int p = __shfl_up_sync(0xFFFFu, u, o);
            if (lane >= o) u += p;
        }
        ws[lane] = u;
    }
    __syncthreads();
    int wpre = (wid > 0) ? ws[wid - 1] : 0;
    if (t < NB) g_bbase[t] = wpre + incl - v;
    if (t == 0) g_off[0] = 0;
}

__global__ void k_apply() {
    __shared__ int ws[8];
    int i = blockIdx.x * 256 + threadIdx.x;
    int lane = threadIdx.x & 31, wid = threadIdx.x >> 5;
    int v = (i < NN) ? g_deg[i] : 0;
    int incl = v;
#pragma unroll
    for (int o = 1; o < 32; o <<= 1) {
        int u = __shfl_up_sync(0xFFFFFFFFu, incl, o);
        if (lane >= o) incl += u;
    }
    if (lane == 31) ws[wid] = incl;
    __syncthreads();
    if (wid == 0 && lane < 8) {
        int u = ws[lane];
#pragma unroll
        for (int o = 1; o < 8; o <<= 1) {
            int p = __shfl_up_sync(0xFFu, u, o);
            if (lane >= o) u += p;
        }
        ws[lane] = u;
    }
    __syncthreads();
    int wpre = (wid > 0) ? ws[wid - 1] : 0;
    if (i < NN) g_off[i + 1] = g_bbase[blockIdx.x] + wpre + incl;
}

__global__ void k_bucket(const int* __restrict__ src, const int* __restrict__ dst) {
    int e = blockIdx.x * blockDim.x + threadIdx.x;
    if (e < EE) {
        int d = dst[e];
        int p = atomicAdd(&g_cur[d], 1);
        g_ssrc[g_off[d] + p] = src[e];
    }
}

// ---------------- fused layer: aggregate + SGEMM(3xTF32) + bias + stats ----------------
// dynamic smem layout (floats):
//   sAgg  [128*132]    16896
//   smA   [2*1536]      3072   (staged A chunks for k>=128; reused as stats stage)
//   smBh  [2*1536]      3072
//   smBl  [2*1536]      3072
//   sMu   [128], sInv [128]
#define FUSED_SMEM ((16896 + 3 * 3072 + 256) * 4)

__global__ void __launch_bounds__(256, 2) k_fused(const float* __restrict__ Xsrc,
                                                  const float* __restrict__ Wh,
                                                  const float* __restrict__ Wl,
                                                  const float* __restrict__ bias,
                                                  float* __restrict__ Yout,
                                                  int slotR, int slotW, int bnPrev) {
    extern __shared__ float sm[];
    float* sAgg = sm;
    float* smA  = sm + 16896;
    float* smBh = sm + 19968;
    float* smBl = sm + 23040;
    float* sMu  = sm + 26112;
    float* sInv = sm + 26240;

    int tid = threadIdx.x;
    int lane = tid & 31, warp = tid >> 5;
    int wm = warp >> 1, wn = warp & 1;
    int m0 = blockIdx.x * 128;

    // local BN stats of previous layer
    if (slotR >= 0 && tid < 128) {
        float mu = g_cs[slotR * 128 + tid] * (1.0f / NN);
        float var = g_cq[slotR * 128 + tid] * (1.0f / NN) - mu * mu;
        sMu[tid] = mu;
        sInv[tid] = rsqrtf(var + BN_EPS);
    }
    __syncthreads();

    // ---- phase 1: mean-aggregate this block's 128 rows into sAgg ----
    {
        float4 m4 = make_float4(0.f, 0.f, 0.f, 0.f);
        float4 iv4 = make_float4(1.f, 1.f, 1.f, 1.f);
        if (bnPrev) {
            m4 = *(const float4*)(sMu + lane * 4);
            iv4 = *(const float4*)(sInv + lane * 4);
        }
        for (int r = warp; r < 128; r += 8) {
            int row = m0 + r;
            float4 acc = make_float4(0.f, 0.f, 0.f, 0.f);
            float4 acc2 = make_float4(0.f, 0.f, 0.f, 0.f);
            if (row < NN) {
                int s = g_off[row], e = g_off[row + 1];
                int j = s;
                for (; j + 1 < e; j += 2) {
                    int s0 = g_ssrc[j];
                    int s1 = g_ssrc[j + 1];
                    float4 v0 = *(const float4*)(Xsrc + (size_t)s0 * HH + lane * 4);
                    float4 v1 = *(const float4*)(Xsrc + (size_t)s1 * HH + lane * 4);
                    if (bnPrev) { v0 = bnrelu4(v0, m4, iv4); v1 = bnrelu4(v1, m4, iv4); }
                    acc.x += v0.x; acc.y += v0.y; acc.z += v0.z; acc.w += v0.w;
                    acc2.x += v1.x; acc2.y += v1.y; acc2.z += v1.z; acc2.w += v1.w;
                }
                if (j < e) {
                    int s0 = g_ssrc[j];
                    float4 v0 = *(const float4*)(Xsrc + (size_t)s0 * HH + lane * 4);
                    if (bnPrev) v0 = bnrelu4(v0, m4, iv4);
                    acc.x += v0.x; acc.y += v0.y; acc.z += v0.z; acc.w += v0.w;
                }
                acc.x += acc2.x; acc.y += acc2.y; acc.z += acc2.z; acc.w += acc2.w;
                float invd = (e > s) ? (1.0f / (float)(e - s)) : 0.0f;
                acc.x *= invd; acc.y *= invd; acc.z *= invd; acc.w *= invd;
            }
            *(float4*)(sAgg + r * 132 + lane * 4) = acc;
        }
    }

    const int lrow = tid >> 1;
    const int lk = (tid & 1) * 4;
    const int grow = m0 + lrow;
    const bool rok = grow < NN;

    // stage B chunk 0
    {
        float4 bh4 = *(const float4*)(Wh + lrow * 256 + lk);
        float4 bl4 = *(const float4*)(Wl + lrow * 256 + lk);
        *(float4*)(smBh + lrow * 12 + lk) = bh4;
        *(float4*)(smBl + lrow * 12 + lk) = bl4;
    }
    __syncthreads();

    float acc[2][8][4];
#pragma unroll
    for (int mt = 0; mt < 2; mt++)
#pragma unroll
        for (int nt = 0; nt < 8; nt++)
#pragma unroll
            for (int j = 0; j < 4; j++) acc[mt][nt][j] = 0.f;

    for (int kc = 0; kc < 32; kc++) {
        float4 a4 = make_float4(0.f, 0.f, 0.f, 0.f);
        float4 bh4, bl4;
        bool havA = false;
        if (kc + 1 < 32) {
            int gk = (kc + 1) * 8 + lk;
            bh4 = *(const float4*)(Wh + lrow * 256 + gk);
            bl4 = *(const float4*)(Wl + lrow * 256 + gk);
            if (kc + 1 >= 16) {
                havA = true;
                int kk = gk - 128;
                if (rok) {
                    float4 v = *(const float4*)(Xsrc + (size_t)grow * HH + kk);
                    if (bnPrev) {
                        float4 m = *(const float4*)(sMu + kk);
                        float4 iv = *(const float4*)(sInv + kk);
                        v = bnrelu4(v, m, iv);
                    }
                    a4 = v;
                }
            }
        }

        uint32_t ah[8], al[8];
        if (kc < 16) {
#pragma unroll
            for (int mt = 0; mt < 2; mt++)
#pragma unroll
                for (int j = 0; j < 4; j++) {
                    int row = wm * 32 + mt * 16 + (lane >> 2) + (j & 1) * 8;
                    int kkg = kc * 8 + (lane & 3) + (j >> 1) * 4;
                    tfsplit(sAgg[row * 132 + kkg], ah[mt * 4 + j], al[mt * 4 + j]);
                }
        } else {
            const float* A = smA + (kc & 1) * 1536;
#pragma unroll
            for (int mt = 0; mt < 2; mt++)
#pragma unroll
                for (int j = 0; j < 4; j++) {
                    int row = wm * 32 + mt * 16 + (lane >> 2) + (j & 1) * 8;
                    int kk = (lane & 3) + (j >> 1) * 4;
                    tfsplit(A[row * 12 + kk], ah[mt * 4 + j], al[mt * 4 + j]);
                }
        }
        const float* Bh = smBh + (kc & 1) * 1536;
        const float* Bl = smBl + (kc & 1) * 1536;
#pragma unroll
        for (int nt = 0; nt < 8; nt++) {
            int n = wn * 64 + nt * 8 + (lane >> 2);
            int kk = lane & 3;
            uint32_t bh0 = __float_as_uint(Bh[n * 12 + kk]);
            uint32_t bh1 = __float_as_uint(Bh[n * 12 + kk + 4]);
            uint32_t bl0 = __float_as_uint(Bl[n * 12 + kk]);
            uint32_t bl1 = __float_as_uint(Bl[n * 12 + kk + 4]);
#pragma unroll
            for (int mt = 0; mt < 2; mt++) {
                mma8(acc[mt][nt], ah + mt * 4, bh0, bh1);
                mma8(acc[mt][nt], ah + mt * 4, bl0, bl1);
                mma8(acc[mt][nt], al + mt * 4, bh0, bh1);
            }
        }

        if (kc + 1 < 32) {
            int nb = (kc + 1) & 1;
            *(float4*)(smBh + nb * 1536 + lrow * 12 + lk) = bh4;
            *(float4*)(smBl + nb * 1536 + lrow * 12 + lk) = bl4;
            if (havA) *(float4*)(smA + nb * 1536 + lrow * 12 + lk) = a4;
        }
        __syncthreads();
    }

    // ---- epilogue: bias, store, column stats ----
    float bc[16];
#pragma unroll
    for (int nt = 0; nt < 8; nt++) {
        int c0 = wn * 64 + nt * 8 + 2 * (lane & 3);
        bc[nt * 2 + 0] = bias[c0];
        bc[nt * 2 + 1] = bias[c0 + 1];
    }

    float s[16], q[16];
#pragma unroll
    for (int j = 0; j < 16; j++) { s[j] = 0.f; q[j] = 0.f; }

#pragma unroll
    for (int mt = 0; mt < 2; mt++) {
        int r0 = m0 + wm * 32 + mt * 16 + (lane >> 2);
        int r1 = r0 + 8;
        bool ok0 = r0 < NN, ok1 = r1 < NN;
#pragma unroll
        for (int nt = 0; nt < 8; nt++) {
            int c0 = wn * 64 + nt * 8 + 2 * (lane & 3);
            float o0 = acc[mt][nt][0] + bc[nt * 2 + 0];
            float o1 = acc[mt][nt][1] + bc[nt * 2 + 1];
            float o2 = acc[mt][nt][2] + bc[nt * 2 + 0];
            float o3 = acc[mt][nt][3] + bc[nt * 2 + 1];
            if (ok0) {
                *(float2*)(Yout + (size_t)r0 * HH + c0) = make_float2(o0, o1);
                s[nt * 2 + 0] += o0; q[nt * 2 + 0] += o0 * o0;
                s[nt * 2 + 1] += o1; q[nt * 2 + 1] += o1 * o1;
            }
            if (ok1) {
                *(float2*)(Yout + (size_t)r1 * HH + c0) = make_float2(o2, o3);
                s[nt * 2 + 0] += o2; q[nt * 2 + 0] += o2 * o2;
                s[nt * 2 + 1] += o3; q[nt * 2 + 1] += o3 * o3;
            }
        }
    }

#pragma unroll
    for (int j = 0; j < 16; j++) {
#pragma unroll
        for (int o = 4; o <= 16; o <<= 1) {
            s[j] += __shfl_xor_sync(0xFFFFFFFFu, s[j], o);
            q[j] += __shfl_xor_sync(0xFFFFFFFFu, q[j], o);
        }
    }

    float* stage = smA;   // free after mainloop
    if (lane < 4) {
#pragma unroll
        for (int nt = 0; nt < 8; nt++) {
            int c = wn * 64 + nt * 8 + 2 * lane;
            stage[warp * 128 + c] = s[nt * 2 + 0];
            stage[warp * 128 + c + 1] = s[nt * 2 + 1];
        }
    }
    __syncthreads();
    if (tid < 128) {
        int cn = tid >> 6;
        float t = stage[(0 * 2 + cn) * 128 + tid] + stage[(1 * 2 + cn) * 128 + tid] +
                  stage[(2 * 2 + cn) * 128 + tid] + stage[(3 * 2 + cn) * 128 + tid];
        atomicAdd(&g_cs[slotW * 128 + tid], t);
    }
    __syncthreads();
    if (lane < 4) {
#pragma unroll
        for (int nt = 0; nt < 8; nt++) {
            int c = wn * 64 + nt * 8 + 2 * lane;
            stage[warp * 128 + c] = q[nt * 2 + 0];
            stage[warp * 128 + c + 1] = q[nt * 2 + 1];
        }
    }
    __syncthreads();
    if (tid < 128) {
        int cn = tid >> 6;
        float t = stage[(0 * 2 + cn) * 128 + tid] + stage[(1 * 2 + cn) * 128 + tid] +
                  stage[(2 * 2 + cn) * 128 + tid] + stage[(3 * 2 + cn) * 128 + tid];
        atomicAdd(&g_cq[slotW * 128 + tid], t);
    }
}

// ---------------- MLP hidden layer GEMM (K=128, bn on input, local stats) ----------------
__global__ void __launch_bounds__(256, 2) k_gemm2(const float* __restrict__ Y,
                                                  const float* __restrict__ Wh,
                                                  const float* __restrict__ Wl,
                                                  const float* __restrict__ bias,
                                                  float* __restrict__ Yout,
                                                  int slotR, int slotW) {
    __shared__ float smA[2][1536];
    __shared__ float smBh[2][1536];
    __shared__ float smBl[2][1536];
    __shared__ float sMu[128], sInv[128];

    int tid = threadIdx.x;
    int lane = tid & 31, warp = tid >> 5;
    int wm = warp >> 1, wn = warp & 1;
    int m0 = blockIdx.x * 128;

    if (tid < 128) {
        float mu = g_cs[slotR * 128 + tid] * (1.0f / NN);
        float var = g_cq[slotR * 128 + tid] * (1.0f / NN) - mu * mu;
        sMu[tid] = mu;
        sInv[tid] = rsqrtf(var + BN_EPS);
    }
    __syncthreads();

    const int lrow = tid >> 1;
    const int lk = (tid & 1) * 4;
    const int grow = m0 + lrow;
    const bool rok = grow < NN;

    float acc[2][8][4];
#pragma unroll
    for (int mt = 0; mt < 2; mt++)
#pragma unroll
        for (int nt = 0; nt < 8; nt++)
#pragma unroll
            for (int j = 0; j < 4; j++) acc[mt][nt][j] = 0.f;

    {
        float4 a4 = make_float4(0.f, 0.f, 0.f, 0.f);
        if (rok) {
            float4 v = *(const float4*)(Y + (size_t)grow * HH + lk);
            float4 m = *(const float4*)(sMu + lk);
            float4 iv = *(const float4*)(sInv + lk);
            a4 = bnrelu4(v, m, iv);
        }
        float4 bh4 = *(const float4*)(Wh + lrow * 128 + lk);
        float4 bl4 = *(const float4*)(Wl + lrow * 128 + lk);
        *(float4*)(&smA[0][lrow * 12 + lk]) = a4;
        *(float4*)(&smBh[0][lrow * 12 + lk]) = bh4;
        *(float4*)(&smBl[0][lrow * 12 + lk]) = bl4;
    }
    __syncthreads();

    for (int kc = 0; kc < 16; kc++) {
        float4 a4 = make_float4(0.f, 0.f, 0.f, 0.f);
        float4 bh4, bl4;
        if (kc + 1 < 16) {
            int gk = (kc + 1) * 8 + lk;
            if (rok) {
                float4 v = *(const float4*)(Y + (size_t)grow * HH + gk);
                float4 m = *(const float4*)(sMu + gk);
                float4 iv = *(const float4*)(sInv + gk);
                a4 = bnrelu4(v, m, iv);
            }
            bh4 = *(const float4*)(Wh + lrow * 128 + gk);
            bl4 = *(const float4*)(Wl + lrow * 128 + gk);
        }

        const float* A = smA[kc & 1];
        const float* Bh = smBh[kc & 1];
        const float* Bl = smBl[kc & 1];

        uint32_t ah[8], al[8];
#pragma unroll
        for (int mt = 0; mt < 2; mt++)
#pragma unroll
            for (int j = 0; j < 4; j++) {
                int row = wm * 32 + mt * 16 + (lane >> 2) + (j & 1) * 8;
                int kk = (lane & 3) + (j >> 1) * 4;
                tfsplit(A[row * 12 + kk], ah[mt * 4 + j], al[mt * 4 + j]);
            }
#pragma unroll
        for (int nt = 0; nt < 8; nt++) {
            int n = wn * 64 + nt * 8 + (lane >> 2);
            int kk = lane & 3;
            uint32_t bh0 = __float_as_uint(Bh[n * 12 + kk]);
            uint32_t bh1 = __float_as_uint(Bh[n * 12 + kk + 4]);
            uint32_t bl0 = __float_as_uint(Bl[n * 12 + kk]);
            uint32_t bl1 = __float_as_uint(Bl[n * 12 + kk + 4]);
#pragma unroll
            for (int mt = 0; mt < 2; mt++) {
                mma8(acc[mt][nt], ah + mt * 4, bh0, bh1);
                mma8(acc[mt][nt], ah + mt * 4, bl0, bl1);
                mma8(acc[mt][nt], al + mt * 4, bh0, bh1);
            }
        }

        if (kc + 1 < 16) {
            int nb = (kc + 1) & 1;
            *(float4*)(&smA[nb][lrow * 12 + lk]) = a4;
            *(float4*)(&smBh[nb][lrow * 12 + lk]) = bh4;
            *(float4*)(&smBl[nb][lrow * 12 + lk]) = bl4;
        }
        __syncthreads();
    }

    float bc[16];
#pragma unroll
    for (int nt = 0; nt < 8; nt++) {
        int c0 = wn * 64 + nt * 8 + 2 * (lane & 3);
        bc[nt * 2 + 0] = bias[c0];
        bc[nt * 2 + 1] = bias[c0 + 1];
    }

    float s[16], q[16];
#pragma unroll
    for (int j = 0; j < 16; j++) { s[j] = 0.f; q[j] = 0.f; }

#pragma unroll
    for (int mt = 0; mt < 2; mt++) {
        int r0 = m0 + wm * 32 + mt * 16 + (lane >> 2);
        int r1 = r0 + 8;
        bool ok0 = r0 < NN, ok1 = r1 < NN;
#pragma unroll
        for (int nt = 0; nt < 8; nt++) {
            int c0 = wn * 64 + nt * 8 + 2 * (lane & 3);
            float o0 = acc[mt][nt][0] + bc[nt * 2 + 0];
            float o1 = acc[mt][nt][1] + bc[nt * 2 + 1];
            float o2 = acc[mt][nt][2] + bc[nt * 2 + 0];
            float o3 = acc[mt][nt][3] + bc[nt * 2 + 1];
            if (ok0) {
                *(float2*)(Yout + (size_t)r0 * HH + c0) = make_float2(o0, o1);
                s[nt * 2 + 0] += o0; q[nt * 2 + 0] += o0 * o0;
                s[nt * 2 + 1] += o1; q[nt * 2 + 1] += o1 * o1;
            }
            if (ok1) {
                *(float2*)(Yout + (size_t)r1 * HH + c0) = make_float2(o2, o3);
                s[nt * 2 + 0] += o2; q[nt * 2 + 0] += o2 * o2;
                s[nt * 2 + 1] += o3; q[nt * 2 + 1] += o3 * o3;
            }
        }
    }

#pragma unroll
    for (int j = 0; j < 16; j++) {
#pragma unroll
        for (int o = 4; o <= 16; o <<= 1) {
            s[j] += __shfl_xor_sync(0xFFFFFFFFu, s[j], o);
            q[j] += __shfl_xor_sync(0xFFFFFFFFu, q[j], o);
        }
    }

    float* stage = smA[0];
    if (lane < 4) {
#pragma unroll
        for (int nt = 0; nt < 8; nt++) {
            int c = wn * 64 + nt * 8 + 2 * lane;
            stage[warp * 128 + c] = s[nt * 2 + 0];
            stage[warp * 128 + c + 1] = s[nt * 2 + 1];
        }
    }
    __syncthreads();
    if (tid < 128) {
        int cn = tid >> 6;
        float t = stage[(0 * 2 + cn) * 128 + tid] + stage[(1 * 2 + cn) * 128 + tid] +
                  stage[(2 * 2 + cn) * 128 + tid] + stage[(3 * 2 + cn) * 128 + tid];
        atomicAdd(&g_cs[slotW * 128 + tid], t);
    }
    __syncthreads();
    if (lane < 4) {
#pragma unroll
        for (int nt = 0; nt < 8; nt++) {
            int c = wn * 64 + nt * 8 + 2 * lane;
            stage[warp * 128 + c] = q[nt * 2 + 0];
            stage[warp * 128 + c + 1] = q[nt * 2 + 1];
        }
    }
    __syncthreads();
    if (tid < 128) {
        int cn = tid >> 6;
        float t = stage[(0 * 2 + cn) * 128 + tid] + stage[(1 * 2 + cn) * 128 + tid] +
                  stage[(2 * 2 + cn) * 128 + tid] + stage[(3 * 2 + cn) * 128 + tid];
        atomicAdd(&g_cq[slotW * 128 + tid], t);
    }
}

// ---------------- final projection (inline BN from slot 3) ----------------
__global__ void k_final(const float* __restrict__ Y, const float* __restrict__ W2,
                        const float* __restrict__ b2, float* __restrict__ out) {
    int w = (blockIdx.x * blockDim.x + threadIdx.x) >> 5;
    int lane = threadIdx.x & 31;
    if (w >= NN) return;
    float4 m4, iv4;
    {
        float mu0 = g_cs[3 * 128 + lane * 4 + 0] * (1.0f / NN);
        float mu1 = g_cs[3 * 128 + lane * 4 + 1] * (1.0f / NN);
        float mu2 = g_cs[3 * 128 + lane * 4 + 2] * (1.0f / NN);
        float mu3 = g_cs[3 * 128 + lane * 4 + 3] * (1.0f / NN);
        m4 = make_float4(mu0, mu1, mu2, mu3);
        iv4.x = rsqrtf(g_cq[3 * 128 + lane * 4 + 0] * (1.0f / NN) - mu0 * mu0 + BN_EPS);
        iv4.y = rsqrtf(g_cq[3 * 128 + lane * 4 + 1] * (1.0f / NN) - mu1 * mu1 + BN_EPS);
        iv4.z = rsqrtf(g_cq[3 * 128 + lane * 4 + 2] * (1.0f / NN) - mu2 * mu2 + BN_EPS);
        iv4.w = rsqrtf(g_cq[3 * 128 + lane * 4 + 3] * (1.0f / NN) - mu3 * mu3 + BN_EPS);
    }
    float4 xv = *(const float4*)(Y + (size_t)w * HH + lane * 4);
    xv = bnrelu4(xv, m4, iv4);
    float4 w0 = *(const float4*)(W2 + lane * 4);
    float4 w1 = *(const float4*)(W2 + HH + lane * 4);
    float d0 = xv.x * w0.x + xv.y * w0.y + xv.z * w0.z + xv.w * w0.w;
    float d1 = xv.x * w1.x + xv.y * w1.y + xv.z * w1.z + xv.w * w1.w;
#pragma unroll
    for (int o = 16; o; o >>= 1) {
        d0 += __shfl_xor_sync(0xFFFFFFFFu, d0, o);
        d1 += __shfl_xor_sync(0xFFFFFFFFu, d1, o);
    }
    if (lane == 0) {
        out[(size_t)w * 2 + 0] = d0 + b2[0];
        out[(size_t)w * 2 + 1] = d1 + b2[1];
    }
}

// ---------------- host launch ----------------
extern "C" void kernel_launch(void* const* d_in, const int* in_sizes, int n_in,
                              void* d_out, int out_size) {
    const float* x   = (const float*)d_in[0];
    const int*   ei  = (const int*)d_in[1];
    const int*   src = ei;
    const int*   dst = ei + EE;
    const float* Wl0 = (const float*)d_in[2];
    const float* bl0 = (const float*)d_in[3];
    const float* Wr0 = (const float*)d_in[4];
    const float* Wl1 = (const float*)d_in[5];
    const float* bl1 = (const float*)d_in[6];
    const float* Wr1 = (const float*)d_in[7];
    const float* Wl2 = (const float*)d_in[8];
    const float* bl2 = (const float*)d_in[9];
    const float* Wr2 = (const float*)d_in[10];
    const float* W1  = (const float*)d_in[11];
    const float* b1  = (const float*)d_in[12];
    const float* W2  = (const float*)d_in[13];
    const float* b2  = (const float*)d_in[14];

    float *wsh_ptr = nullptr, *wsl_ptr = nullptr, *ws1h_ptr = nullptr, *ws1l_ptr = nullptr;
    float *y0_ptr = nullptr, *y1_ptr = nullptr;
    cudaGetSymbolAddress((void**)&wsh_ptr, g_wsh);
    cudaGetSymbolAddress((void**)&wsl_ptr, g_wsl);
    cudaGetSymbolAddress((void**)&ws1h_ptr, g_ws1h);
    cudaGetSymbolAddress((void**)&ws1l_ptr, g_ws1l);
    cudaGetSymbolAddress((void**)&y0_ptr, g_y0);
    cudaGetSymbolAddress((void**)&y1_ptr, g_y1);

    static int attr_set = 0;
    if (!attr_set) {
        cudaFuncSetAttribute(k_fused, cudaFuncAttributeMaxDynamicSharedMemorySize, FUSED_SMEM);
        attr_set = 1;
    }

    // prologue + CSR build
    k_split<<<448, 256>>>(Wl0, Wr0, Wl1, Wr1, Wl2, Wr2, W1);
    k_count<<<(EE + 255) / 256, 256>>>(dst);
    k_part<<<NB, 256>>>();
    k_scanp<<<1, 512>>>();
    k_apply<<<NB, 256>>>();
    k_bucket<<<(EE + 255) / 256, 256>>>(src, dst);

    const int LSTRIDE = 128 * 256;

    // layer 0: gather raw x -> Y0, stats slot 0
    k_fused<<<GB, 256, FUSED_SMEM>>>(x, wsh_ptr, wsl_ptr, bl0, y0_ptr, -1, 0, 0);
    // layer 1: gather bnrelu(Y0) -> Y1, read slot 0, write slot 1
    k_fused<<<GB, 256, FUSED_SMEM>>>(y0_ptr, wsh_ptr + LSTRIDE, wsl_ptr + LSTRIDE, bl1,
                                     y1_ptr, 0, 1, 1);
    // layer 2: gather bnrelu(Y1) -> Y0, read slot 1, write slot 2
    k_fused<<<GB, 256, FUSED_SMEM>>>(y1_ptr, wsh_ptr + 2 * LSTRIDE, wsl_ptr + 2 * LSTRIDE, bl2,
                                     y0_ptr, 1, 2, 1);
    // MLP hidden: bnrelu(Y0) @ W1^T + b1 -> Y1, read slot 2, write slot 3
    k_gemm2<<<GB, 256>>>(y0_ptr, ws1h_ptr, ws1l_ptr, b1, y1_ptr, 2, 3);
    // output projection from bnrelu(Y1) with slot-3 stats
    k_final<<<(NN * 32 + 255) / 256, 256>>>(y1_ptr, W2, b2, (float*)d_out);
}

// round 8
// speedup vs baseline: 1.6488x; 1.6488x over previous
#include <cuda_runtime.h>
#include <cstdint>

#define NN 100000
#define EE 640000
#define HH 128
#define BN_EPS 1e-5f
#define NB 391            // ceil(NN/256)
#define GB 782            // ceil(NN/128)

// ---------------- device scratch ----------------
__device__ __align__(16) float g_agg[(size_t)NN * HH];
__device__ __align__(16) float g_y[(size_t)NN * HH];
__device__ __align__(16) uint32_t g_bwh[3 * 128 * 128];  // layers 0-2 bf16-hi packed [layer][n][kp] (K=256 -> 128 u32)
__device__ __align__(16) uint32_t g_bwl[3 * 128 * 128];  // bf16-lo
__device__ __align__(16) uint32_t g_b1h[128 * 64];       // W1 hi packed (K=128 -> 64 u32)
__device__ __align__(16) uint32_t g_b1l[128 * 64];
__device__ int   g_deg[NN];
__device__ int   g_off[NN + 1];
__device__ int   g_cur[NN];
__device__ int   g_ssrc[EE];
__device__ int   g_bpart[512];
__device__ int   g_bbase[512];
__device__ __align__(16) float g_cs[4 * 128];
__device__ __align__(16) float g_cq[4 * 128];

// ---------------- bf16 split helpers ----------------
__device__ __forceinline__ void bfsplit2(float v0, float v1, uint32_t& hp, uint32_t& lp) {
    uint32_t h;
    asm("cvt.rn.bf16x2.f32 %0, %1, %2;" : "=r"(h) : "f"(v1), "f"(v0));  // v0 -> low half
    float h0 = __uint_as_float(h << 16);
    float h1 = __uint_as_float(h & 0xFFFF0000u);
    float l0 = v0 - h0;
    float l1 = v1 - h1;
    uint32_t l;
    asm("cvt.rn.bf16x2.f32 %0, %1, %2;" : "=r"(l) : "f"(l1), "f"(l0));
    hp = h; lp = l;
}

__device__ __forceinline__ void mma16(float* c, const uint32_t* a, uint32_t b0, uint32_t b1) {
    asm("mma.sync.aligned.m16n8k16.row.col.f32.bf16.bf16.f32 "
        "{%0,%1,%2,%3},{%4,%5,%6,%7},{%8,%9},{%0,%1,%2,%3};"
        : "+f"(c[0]), "+f"(c[1]), "+f"(c[2]), "+f"(c[3])
        : "r"(a[0]), "r"(a[1]), "r"(a[2]), "r"(a[3]), "r"(b0), "r"(b1));
}

__device__ __forceinline__ float4 bnrelu4(float4 v, float4 m, float4 iv) {
    v.x = fmaxf(0.f, (v.x - m.x) * iv.x);
    v.y = fmaxf(0.f, (v.y - m.y) * iv.y);
    v.z = fmaxf(0.f, (v.z - m.z) * iv.z);
    v.w = fmaxf(0.f, (v.w - m.w) * iv.w);
    return v;
}

// ---------------- prologue: weight bf16-split + zero deg/cur/stats ----------------
__global__ void k_split(const float* __restrict__ Wl0, const float* __restrict__ Wr0,
                        const float* __restrict__ Wl1, const float* __restrict__ Wr1,
                        const float* __restrict__ Wl2, const float* __restrict__ Wr2,
                        const float* __restrict__ W1) {
    int i = blockIdx.x * 256 + threadIdx.x;
    if (i < NN) { g_deg[i] = 0; g_cur[i] = 0; }
    if (i < 512) { g_cs[i] = 0.f; g_cq[i] = 0.f; }
    if (i < 3 * 128 * 128) {
        int layer = i >> 14;
        int r = i & 16383;            // n*128 + kp
        int n = r >> 7;
        int kp = r & 127;
        int gk = kp * 2;
        const float* W;
        int k = gk;
        if (gk < 128) {
            W = (layer == 0) ? Wl0 : ((layer == 1) ? Wl1 : Wl2);
        } else {
            W = (layer == 0) ? Wr0 : ((layer == 1) ? Wr1 : Wr2);
            k = gk - 128;
        }
        float v0 = W[n * 128 + k];
        float v1 = W[n * 128 + k + 1];
        bfsplit2(v0, v1, g_bwh[i], g_bwl[i]);
    } else if (i < 3 * 128 * 128 + 128 * 64) {
        int j = i - 49152;
        int n = j >> 6, kp = j & 63;
        bfsplit2(W1[n * 128 + kp * 2], W1[n * 128 + kp * 2 + 1], g_b1h[j], g_b1l[j]);
    }
}

// ---------------- CSR build ----------------
__global__ void k_count(const int* __restrict__ dst) {
    int e = blockIdx.x * blockDim.x + threadIdx.x;
    if (e < EE) atomicAdd(&g_deg[dst[e]], 1);
}

__global__ void k_part() {
    __shared__ int ws[8];
    int i = blockIdx.x * 256 + threadIdx.x;
    int v = (i < NN) ? g_deg[i] : 0;
    int lane = threadIdx.x & 31, wid = threadIdx.x >> 5;
    int s = v;
#pragma unroll
    for (int o = 16; o; o >>= 1) s += __shfl_xor_sync(0xFFFFFFFFu, s, o);
    if (lane == 0) ws[wid] = s;
    __syncthreads();
    if (threadIdx.x == 0) {
        int t = 0;
#pragma unroll
        for (int w = 0; w < 8; w++) t += ws[w];
        g_bpart[blockIdx.x] = t;
    }
}

__global__ void k_scanp() {
    __shared__ int ws[16];
    int t = threadIdx.x;
    int lane = t & 31, wid = t >> 5;
    int v = (t < NB) ? g_bpart[t] : 0;
    int incl = v;
#pragma unroll
    for (int o = 1; o < 32; o <<= 1) {
        int u = __shfl_up_sync(0xFFFFFFFFu, incl, o);
        if (lane >= o) incl += u;
    }
    if (lane == 31) ws[wid] = incl;
    __syncthreads();
    if (wid == 0 && lane < 16) {
        int u = ws[lane];
#pragma unroll
        for (int o = 1; o < 16; o <<= 1) {
            int p = __shfl_up_sync(0xFFFFu, u, o);
            if (lane >= o) u += p;
        }
        ws[lane] = u;
    }
    __syncthreads();
    int wpre = (wid > 0) ? ws[wid - 1] : 0;
    if (t < NB) g_bbase[t] = wpre + incl - v;
    if (t == 0) g_off[0] = 0;
}

__global__ void k_apply() {
    __shared__ int ws[8];
    int i = blockIdx.x * 256 + threadIdx.x;
    int lane = threadIdx.x & 31, wid = threadIdx.x >> 5;
    int v = (i < NN) ? g_deg[i] : 0;
    int incl = v;
#pragma unroll
    for (int o = 1; o < 32; o <<= 1) {
        int u = __shfl_up_sync(0xFFFFFFFFu, incl, o);
        if (lane >= o) incl += u;
    }
    if (lane == 31) ws[wid] = incl;
    __syncthreads();
    if (wid == 0 && lane < 8) {
        int u = ws[lane];
#pragma unroll
        for (int o = 1; o < 8; o <<= 1) {
            int p = __shfl_up_sync(0xFFu, u, o);
            if (lane >= o) u += p;
        }
        ws[lane] = u;
    }
    __syncthreads();
    int wpre = (wid > 0) ? ws[wid - 1] : 0;
    if (i < NN) g_off[i + 1] = g_bbase[blockIdx.x] + wpre + incl;
}

__global__ void k_bucket(const int* __restrict__ src, const int* __restrict__ dst) {
    int e = blockIdx.x * blockDim.x + threadIdx.x;
    if (e < EE) {
        int d = dst[e];
        int p = atomicAdd(&g_cur[d], 1);
        g_ssrc[g_off[d] + p] = src[e];
    }
}

// ---------------- mean aggregation (slot-based BN+ReLU on the read) ----------------
__global__ void k_agg(const float* __restrict__ X, int slotR) {
    int w = (blockIdx.x * blockDim.x + threadIdx.x) >> 5;
    int lane = threadIdx.x & 31;
    if (w >= NN) return;
    int bn = slotR >= 0;
    float4 m4 = make_float4(0.f, 0.f, 0.f, 0.f);
    float4 iv4 = make_float4(1.f, 1.f, 1.f, 1.f);
    if (bn) {
        float4 cs = *(const float4*)(g_cs + slotR * 128 + lane * 4);
        float4 cq = *(const float4*)(g_cq + slotR * 128 + lane * 4);
        m4 = make_float4(cs.x * (1.0f / NN), cs.y * (1.0f / NN),
                         cs.z * (1.0f / NN), cs.w * (1.0f / NN));
        iv4.x = rsqrtf(cq.x * (1.0f / NN) - m4.x * m4.x + BN_EPS);
        iv4.y = rsqrtf(cq.y * (1.0f / NN) - m4.y * m4.y + BN_EPS);
        iv4.z = rsqrtf(cq.z * (1.0f / NN) - m4.z * m4.z + BN_EPS);
        iv4.w = rsqrtf(cq.w * (1.0f / NN) - m4.w * m4.w + BN_EPS);
    }
    int s = g_off[w], e = g_off[w + 1];
    float4 acc = make_float4(0.f, 0.f, 0.f, 0.f);
    float4 acc2 = make_float4(0.f, 0.f, 0.f, 0.f);
    int j = s;
    for (; j + 1 < e; j += 2) {
        int s0 = g_ssrc[j];
        int s1 = g_ssrc[j + 1];
        float4 v0 = *(const float4*)(X + (size_t)s0 * HH + lane * 4);
        float4 v1 = *(const float4*)(X + (size_t)s1 * HH + lane * 4);
        if (bn) { v0 = bnrelu4(v0, m4, iv4); v1 = bnrelu4(v1, m4, iv4); }
        acc.x += v0.x; acc.y += v0.y; acc.z += v0.z; acc.w += v0.w;
        acc2.x += v1.x; acc2.y += v1.y; acc2.z += v1.z; acc2.w += v1.w;
    }
    if (j < e) {
        int s0 = g_ssrc[j];
        float4 v0 = *(const float4*)(X + (size_t)s0 * HH + lane * 4);
        if (bn) v0 = bnrelu4(v0, m4, iv4);
        acc.x += v0.x; acc.y += v0.y; acc.z += v0.z; acc.w += v0.w;
    }
    acc.x += acc2.x; acc.y += acc2.y; acc.z += acc2.z; acc.w += acc2.w;
    float invd = (e > s) ? (1.0f / (float)(e - s)) : 0.0f;
    acc.x *= invd; acc.y *= invd; acc.z *= invd; acc.w *= invd;
    *(float4*)(g_agg + (size_t)w * HH + lane * 4) = acc;
}

// ---------------- bf16 double-split GEMM + bias + stats epilogue ----------------
// block 128x128, 8 warps (warp tile 32x64), K chunk 16, planes stride 12 (u32)
__global__ void __launch_bounds__(256, 2) k_gemm(const float* __restrict__ PA,
                                                 const float* __restrict__ PB,
                                                 const uint32_t* __restrict__ Wph,
                                                 const uint32_t* __restrict__ Wpl,
                                                 const float* __restrict__ bias,
                                                 float* __restrict__ Yout,
                                                 int Ktot, int bnA, int bnB,
                                                 int slotR, int slotW) {
    __shared__ uint32_t uAh[2][128 * 12];
    __shared__ uint32_t uAl[2][128 * 12];
    __shared__ uint32_t uBh[2][128 * 12];
    __shared__ uint32_t uBl[2][128 * 12];
    __shared__ float sMu[128], sInv[128];

    int tid = threadIdx.x;
    int lane = tid & 31, warp = tid >> 5;
    int wm = warp >> 1, wn = warp & 1;
    int m0 = blockIdx.x * 128;
    int nch = Ktot / 16;
    int wstride = Ktot / 2;

    if ((bnA || bnB) && tid < 128) {
        float mu = g_cs[slotR * 128 + tid] * (1.0f / NN);
        float var = g_cq[slotR * 128 + tid] * (1.0f / NN) - mu * mu;
        sMu[tid] = mu;
        sInv[tid] = rsqrtf(var + BN_EPS);
    }
    __syncthreads();

    const int lrow = tid >> 1;          // 0..127 (A row / B n)
    const int kh = tid & 1;             // which k-half of the 16-chunk
    const int grow = m0 + lrow;
    const bool rok = grow < NN;

    float acc[2][8][4];
#pragma unroll
    for (int mt = 0; mt < 2; mt++)
#pragma unroll
        for (int nt = 0; nt < 8; nt++)
#pragma unroll
            for (int j = 0; j < 4; j++) acc[mt][nt][j] = 0.f;

    // ---- fill helper (inline): chunk kc -> buffer buf ----
    // A: row lrow, k = kc*16 + kh*8 .. +8 ; B: n lrow, 4 u32 from plane
#define FILL_CHUNK(kc, buf)                                                          \
    {                                                                                \
        int gk = (kc) * 16 + kh * 8;                                                 \
        float4 v0 = make_float4(0.f, 0.f, 0.f, 0.f);                                 \
        float4 v1 = make_float4(0.f, 0.f, 0.f, 0.f);                                 \
        if (rok) {                                                                   \
            const float* S; int kk; int bn;                                          \
            if (gk < 128) { S = PA; kk = gk; bn = bnA; }                             \
            else          { S = PB; kk = gk - 128; bn = bnB; }                       \
            v0 = *(const float4*)(S + (size_t)grow * HH + kk);                       \
            v1 = *(const float4*)(S + (size_t)grow * HH + kk + 4);                   \
            if (bn) {                                                                \
                float4 mm0 = *(const float4*)(sMu + kk);                             \
                float4 ii0 = *(const float4*)(sInv + kk);                            \
                float4 mm1 = *(const float4*)(sMu + kk + 4);                         \
                float4 ii1 = *(const float4*)(sInv + kk + 4);                        \
                v0 = bnrelu4(v0, mm0, ii0);                                          \
                v1 = bnrelu4(v1, mm1, ii1);                                          \
            }                                                                        \
        }                                                                            \
        uint32_t h0, h1, h2, h3, l0, l1, l2, l3;                                     \
        bfsplit2(v0.x, v0.y, h0, l0);                                                \
        bfsplit2(v0.z, v0.w, h1, l1);                                                \
        bfsplit2(v1.x, v1.y, h2, l2);                                                \
        bfsplit2(v1.z, v1.w, h3, l3);                                                \
        *(uint4*)(&uAh[buf][lrow * 12 + kh * 4]) = make_uint4(h0, h1, h2, h3);       \
        *(uint4*)(&uAl[buf][lrow * 12 + kh * 4]) = make_uint4(l0, l1, l2, l3);       \
        uint4 bh = *(const uint4*)(Wph + lrow * wstride + (kc) * 8 + kh * 4);        \
        uint4 bl = *(const uint4*)(Wpl + lrow * wstride + (kc) * 8 + kh * 4);        \
        *(uint4*)(&uBh[buf][lrow * 12 + kh * 4]) = bh;                               \
        *(uint4*)(&uBl[buf][lrow * 12 + kh * 4]) = bl;                               \
    }

    FILL_CHUNK(0, 0);
    __syncthreads();

    for (int kc = 0; kc < nch; kc++) {
        int cur = kc & 1;

        uint32_t ah[8], al[8];
#pragma unroll
        for (int mt = 0; mt < 2; mt++)
#pragma unroll
            for (int j = 0; j < 4; j++) {
                int row = wm * 32 + mt * 16 + (lane >> 2) + (j & 1) * 8;
                int kp = (lane & 3) + (j >> 1) * 4;
                ah[mt * 4 + j] = uAh[cur][row * 12 + kp];
                al[mt * 4 + j] = uAl[cur][row * 12 + kp];
            }
#pragma unroll
        for (int nt = 0; nt < 8; nt++) {
            int n = wn * 64 + nt * 8 + (lane >> 2);
            int kp = lane & 3;
            uint32_t bh0 = uBh[cur][n * 12 + kp];
            uint32_t bh1 = uBh[cur][n * 12 + kp + 4];
            uint32_t bl0 = uBl[cur][n * 12 + kp];
            uint32_t bl1 = uBl[cur][n * 12 + kp + 4];
#pragma unroll
            for (int mt = 0; mt < 2; mt++) {
                mma16(acc[mt][nt], ah + mt * 4, bh0, bh1);
                mma16(acc[mt][nt], ah + mt * 4, bl0, bl1);
                mma16(acc[mt][nt], al + mt * 4, bh0, bh1);
            }
        }

        if (kc + 1 < nch) {
            FILL_CHUNK(kc + 1, (kc + 1) & 1);
        }
        __syncthreads();
    }
#undef FILL_CHUNK

    // ---- epilogue: bias, store, column stats ----
    float bc[16];
#pragma unroll
    for (int nt = 0; nt < 8; nt++) {
        int c0 = wn * 64 + nt * 8 + 2 * (lane & 3);
        bc[nt * 2 + 0] = bias[c0];
        bc[nt * 2 + 1] = bias[c0 + 1];
    }

    float s[16], q[16];
#pragma unroll
    for (int j = 0; j < 16; j++) { s[j] = 0.f; q[j] = 0.f; }

#pragma unroll
    for (int mt = 0; mt < 2; mt++) {
        int r0 = m0 + wm * 32 + mt * 16 + (lane >> 2);
        int r1 = r0 + 8;
        bool ok0 = r0 < NN, ok1 = r1 < NN;
#pragma unroll
        for (int nt = 0; nt < 8; nt++) {
            int c0 = wn * 64 + nt * 8 + 2 * (lane & 3);
            float o0 = acc[mt][nt][0] + bc[nt * 2 + 0];
            float o1 = acc[mt][nt][1] + bc[nt * 2 + 1];
            float o2 = acc[mt][nt][2] + bc[nt * 2 + 0];
            float o3 = acc[mt][nt][3] + bc[nt * 2 + 1];
            if (ok0) {
                *(float2*)(Yout + (size_t)r0 * HH + c0) = make_float2(o0, o1);
                s[nt * 2 + 0] += o0; q[nt * 2 + 0] += o0 * o0;
                s[nt * 2 + 1] += o1; q[nt * 2 + 1] += o1 * o1;
            }
            if (ok1) {
                *(float2*)(Yout + (size_t)r1 * HH + c0) = make_float2(o2, o3);
                s[nt * 2 + 0] += o2; q[nt * 2 + 0] += o2 * o2;
                s[nt * 2 + 1] += o3; q[nt * 2 + 1] += o3 * o3;
            }
        }
    }

#pragma unroll
    for (int j = 0; j < 16; j++) {
#pragma unroll
        for (int o = 4; o <= 16; o <<= 1) {
            s[j] += __shfl_xor_sync(0xFFFFFFFFu, s[j], o);
            q[j] += __shfl_xor_sync(0xFFFFFFFFu, q[j], o);
        }
    }

    float* stage = (float*)uAh[0];   // reuse: [8 warps][128 cols]
    if (lane < 4) {
#pragma unroll
        for (int nt = 0; nt < 8; nt++) {
            int c = wn * 64 + nt * 8 + 2 * lane;
            stage[warp * 128 + c] = s[nt * 2 + 0];
            stage[warp * 128 + c + 1] = s[nt * 2 + 1];
        }
    }
    __syncthreads();
    if (tid < 128) {
        int cn = tid >> 6;
        float t = stage[(0 * 2 + cn) * 128 + tid] + stage[(1 * 2 + cn) * 128 + tid] +
                  stage[(2 * 2 + cn) * 128 + tid] + stage[(3 * 2 + cn) * 128 + tid];
        atomicAdd(&g_cs[slotW * 128 + tid], t);
    }
    __syncthreads();
    if (lane < 4) {
#pragma unroll
        for (int nt = 0; nt < 8; nt++) {
            int c = wn * 64 + nt * 8 + 2 * lane;
            stage[warp * 128 + c] = q[nt * 2 + 0];
            stage[warp * 128 + c + 1] = q[nt * 2 + 1];
        }
    }
    __syncthreads();
    if (tid < 128) {
        int cn = tid >> 6;
        float t = stage[(0 * 2 + cn) * 128 + tid] + stage[(1 * 2 + cn) * 128 + tid] +
                  stage[(2 * 2 + cn) * 128 + tid] + stage[(3 * 2 + cn) * 128 + tid];
        atomicAdd(&g_cq[slotW * 128 + tid], t);
    }
}

// ---------------- final projection (inline BN from slot 3) ----------------
__global__ void k_final(const float* __restrict__ Y, const float* __restrict__ W2,
                        const float* __restrict__ b2, float* __restrict__ out) {
    int w = (blockIdx.x * blockDim.x + threadIdx.x) >> 5;
    int lane = threadIdx.x & 31;
    if (w >= NN) return;
    float4 m4, iv4;
    {
        float4 cs = *(const float4*)(g_cs + 3 * 128 + lane * 4);
        float4 cq = *(const float4*)(g_cq + 3 * 128 + lane * 4);
        m4 = make_float4(cs.x * (1.0f / NN), cs.y * (1.0f / NN),
                         cs.z * (1.0f / NN), cs.w * (1.0f / NN));
        iv4.x = rsqrtf(cq.x * (1.0f / NN) - m4.x * m4.x + BN_EPS);
        iv4.y = rsqrtf(cq.y * (1.0f / NN) - m4.y * m4.y + BN_EPS);
        iv4.z = rsqrtf(cq.z * (1.0f / NN) - m4.z * m4.z + BN_EPS);
        iv4.w = rsqrtf(cq.w * (1.0f / NN) - m4.w * m4.w + BN_EPS);
    }
    float4 xv = *(const float4*)(Y + (size_t)w * HH + lane * 4);
    xv = bnrelu4(xv, m4, iv4);
    float4 w0 = *(const float4*)(W2 + lane * 4);
    float4 w1 = *(const float4*)(W2 + HH + lane * 4);
    float d0 = xv.x * w0.x + xv.y * w0.y + xv.z * w0.z + xv.w * w0.w;
    float d1 = xv.x * w1.x + xv.y * w1.y + xv.z * w1.z + xv.w * w1.w;
#pragma unroll
    for (int o = 16; o; o >>= 1) {
        d0 += __shfl_xor_sync(0xFFFFFFFFu, d0, o);
        d1 += __shfl_xor_sync(0xFFFFFFFFu, d1, o);
    }
    if (lane == 0) {
        out[(size_t)w * 2 + 0] = d0 + b2[0];
        out[(size_t)w * 2 + 1] = d1 + b2[1];
    }
}

// ---------------- host launch ----------------
extern "C" void kernel_launch(void* const* d_in, const int* in_sizes, int n_in,
                              void* d_out, int out_size) {
    const float* x   = (const float*)d_in[0];
    const int*   ei  = (const int*)d_in[1];
    const int*   src = ei;
    const int*   dst = ei + EE;
    const float* Wl0 = (const float*)d_in[2];
    const float* bl0 = (const float*)d_in[3];
    const float* Wr0 = (const float*)d_in[4];
    const float* Wl1 = (const float*)d_in[5];
    const float* bl1 = (const float*)d_in[6];
    const float* Wr1 = (const float*)d_in[7];
    const float* Wl2 = (const float*)d_in[8];
    const float* bl2 = (const float*)d_in[9];
    const float* Wr2 = (const float*)d_in[10];
    const float* W1  = (const float*)d_in[11];
    const float* b1  = (const float*)d_in[12];
    const float* W2  = (const float*)d_in[13];
    const float* b2  = (const float*)d_in[14];

    uint32_t *bwh = nullptr, *bwl = nullptr, *b1h = nullptr, *b1l = nullptr;
    float *agg_ptr = nullptr, *y_ptr = nullptr;
    cudaGetSymbolAddress((void**)&bwh, g_bwh);
    cudaGetSymbolAddress((void**)&bwl, g_bwl);
    cudaGetSymbolAddress((void**)&b1h, g_b1h);
    cudaGetSymbolAddress((void**)&b1l, g_b1l);
    cudaGetSymbolAddress((void**)&agg_ptr, g_agg);
    cudaGetSymbolAddress((void**)&y_ptr, g_y);

    // prologue + CSR build
    k_split<<<NB, 256>>>(Wl0, Wr0, Wl1, Wr1, Wl2, Wr2, W1);
    k_count<<<(EE + 255) / 256, 256>>>(dst);
    k_part<<<NB, 256>>>();
    k_scanp<<<1, 512>>>();
    k_apply<<<NB, 256>>>();
    k_bucket<<<(EE + 255) / 256, 256>>>(src, dst);

    const int AGG_BLOCKS = (NN * 32 + 255) / 256;
    const int LSTRIDE = 128 * 128;   // u32 per layer per plane

    // layer 0: gather raw x; GEMM over [agg | x]
    k_agg<<<AGG_BLOCKS, 256>>>(x, -1);
    k_gemm<<<GB, 256>>>(agg_ptr, x, bwh, bwl, bl0, y_ptr, 256, 0, 0, -1, 0);

    // layer 1: gather bnrelu(y, slot0); GEMM over [agg | bnrelu(y)]
    k_agg<<<AGG_BLOCKS, 256>>>(y_ptr, 0);
    k_gemm<<<GB, 256>>>(agg_ptr, y_ptr, bwh + LSTRIDE, bwl + LSTRIDE, bl1, y_ptr,
                        256, 0, 1, 0, 1);

    // layer 2
    k_agg<<<AGG_BLOCKS, 256>>>(y_ptr, 1);
    k_gemm<<<GB, 256>>>(agg_ptr, y_ptr, bwh + 2 * LSTRIDE, bwl + 2 * LSTRIDE, bl2, y_ptr,
                        256, 0, 1, 1, 2);

    // MLP hidden: bnrelu(y, slot2) @ W1^T + b1
    k_gemm<<<GB, 256>>>(y_ptr, nullptr, b1h, b1l, b1, y_ptr, 128, 1, 0, 2, 3);

    // output projection with slot-3 stats
    k_final<<<AGG_BLOCKS, 256>>>(y_ptr, W2, b2, (float*)d_out);
}